// round 1
// baseline (speedup 1.0000x reference)
#include <cuda_runtime.h>
#include <math.h>

// Problem constants
#define NROWS 32768   // B*H*W
#define DDIM  64
#define MCODE 1024
#define HWSZ  1024    // H*W

// Output layout (fp32): z_q_out [0,2097152) | loss [2097152] | ind [2097153, 2129921)
#define ZQ_ELEMS 2097152

// Static device scratch (no allocations allowed)
__device__ float g_zf[NROWS * DDIM];     // (N, D) row-major, transposed z
__device__ float g_dmin[NROWS];          // min distance per row
__device__ float g_y2[MCODE];            // per-code squared norm
__device__ float g_s[2048];              // s[b, d] partial sums (B=32 x D=64)

// ---------------------------------------------------------------------------
// Kernel 1: transpose z (B, D, H, W) -> zf (N, D),  N = b*HW + hw
// Per b: transpose a 64 x 1024 matrix into 1024 x 64. Classic 32x32 tile.
// grid (32 hw-tiles, 2 d-tiles, 32 b), block (32, 8)
// ---------------------------------------------------------------------------
__global__ void transpose_kernel(const float* __restrict__ z) {
    __shared__ float tile[32][33];
    int b   = blockIdx.z;
    int hw0 = blockIdx.x * 32;
    int d0  = blockIdx.y * 32;
    const float* zb = z + (size_t)b * (DDIM * HWSZ);
    float* ob = g_zf + (size_t)b * (HWSZ * DDIM);
    #pragma unroll
    for (int i = threadIdx.y; i < 32; i += 8)
        tile[i][threadIdx.x] = zb[(d0 + i) * HWSZ + hw0 + threadIdx.x];
    __syncthreads();
    #pragma unroll
    for (int i = threadIdx.y; i < 32; i += 8)
        ob[(hw0 + i) * DDIM + d0 + threadIdx.x] = tile[threadIdx.x][i];
}

// ---------------------------------------------------------------------------
// Kernel 2: y2[m] = sum_k codebook[m][k]^2
// ---------------------------------------------------------------------------
__global__ void y2_kernel(const float* __restrict__ cb) {
    int c = blockIdx.x * blockDim.x + threadIdx.x;
    if (c < MCODE) {
        const float4* p = (const float4*)(cb + c * DDIM);
        float s = 0.f;
        #pragma unroll
        for (int q = 0; q < DDIM / 4; ++q) {
            float4 v = p[q];
            s += v.x * v.x + v.y * v.y + v.z * v.z + v.w * v.w;
        }
        g_y2[c] = s;
    }
}

// ---------------------------------------------------------------------------
// Kernel 3: fused distance GEMM + argmin.
// Tile: 128 rows x 128 codes per iteration, 8 code-tiles (M=1024).
// 256 threads, each computes an 8x8 micro-tile of dot products, then
// dist = (x2 + y2) - 2*dot, tracks running (min, argmin) per row.
// Shared memory (dynamic, 66560 B):
//   As [64][128] k-major (33 KB), Bs [64][128] (33 KB, reused as reduction
//   buffer after the main loop), y2s[128], x2s[128].
// ---------------------------------------------------------------------------
#define GEMM_SMEM ((2 * 64 * 128 + 256) * 4)

__global__ __launch_bounds__(256, 2)
void gemm_argmin_kernel(const float* __restrict__ cb, float* __restrict__ out_ind) {
    extern __shared__ float sm[];
    float* As  = sm;                   // [64][128] : As[k*128 + row]
    float* Bs  = sm + 64 * 128;        // [64][128] : Bs[k*128 + code]
    float* y2s = sm + 2 * 64 * 128;    // [128]
    float* x2s = y2s + 128;            // [128]
    float* redv = Bs;                  // alias after compute: [128][16]
    int*   redi = (int*)(Bs + 2048);   // alias: [128][16]

    int tid = threadIdx.x;
    int tx = tid & 15;      // code group (8 codes each)
    int ty = tid >> 4;      // row group  (8 rows each)
    int row0 = blockIdx.x * 128;
    int lr = tid & 15;      // loader: row within group of 16
    int kq = tid >> 4;      // loader: k-quad (4 floats)

    // Load A tile (rows row0..row0+127, all K=64) transposed into smem
    #pragma unroll
    for (int it = 0; it < 8; ++it) {
        int r = it * 16 + lr;
        float4 v = *(const float4*)&g_zf[(row0 + r) * 64 + kq * 4];
        As[(kq * 4 + 0) * 128 + r] = v.x;
        As[(kq * 4 + 1) * 128 + r] = v.y;
        As[(kq * 4 + 2) * 128 + r] = v.z;
        As[(kq * 4 + 3) * 128 + r] = v.w;
    }
    __syncthreads();

    // x2 per row (from smem A tile)
    if (tid < 128) {
        float s = 0.f;
        #pragma unroll
        for (int k = 0; k < 64; ++k) { float a = As[k * 128 + tid]; s += a * a; }
        x2s[tid] = s;
    }

    float best[8];
    int   bidx[8];
    #pragma unroll
    for (int i = 0; i < 8; ++i) { best[i] = 3.4028235e38f; bidx[i] = 0; }

    for (int t = 0; t < 8; ++t) {
        __syncthreads();   // protect Bs/y2s (and x2s on t==0)
        int c0 = t * 128;
        #pragma unroll
        for (int it = 0; it < 8; ++it) {
            int r = it * 16 + lr;
            float4 v = *(const float4*)&cb[(c0 + r) * 64 + kq * 4];
            Bs[(kq * 4 + 0) * 128 + r] = v.x;
            Bs[(kq * 4 + 1) * 128 + r] = v.y;
            Bs[(kq * 4 + 2) * 128 + r] = v.z;
            Bs[(kq * 4 + 3) * 128 + r] = v.w;
        }
        if (tid < 128) y2s[tid] = g_y2[c0 + tid];
        __syncthreads();

        float acc[8][8];
        #pragma unroll
        for (int i = 0; i < 8; ++i)
            #pragma unroll
            for (int j = 0; j < 8; ++j) acc[i][j] = 0.f;

        #pragma unroll 8
        for (int k = 0; k < 64; ++k) {
            float4 a0 = *(const float4*)&As[k * 128 + ty * 8];
            float4 a1 = *(const float4*)&As[k * 128 + ty * 8 + 4];
            float4 b0 = *(const float4*)&Bs[k * 128 + tx * 8];
            float4 b1 = *(const float4*)&Bs[k * 128 + tx * 8 + 4];
            float a[8] = {a0.x, a0.y, a0.z, a0.w, a1.x, a1.y, a1.z, a1.w};
            float bb[8] = {b0.x, b0.y, b0.z, b0.w, b1.x, b1.y, b1.z, b1.w};
            #pragma unroll
            for (int i = 0; i < 8; ++i)
                #pragma unroll
                for (int j = 0; j < 8; ++j)
                    acc[i][j] += a[i] * bb[j];
        }

        // dist = (x2 + y2) - 2*dot ; running min with first-index tie semantics
        #pragma unroll
        for (int i = 0; i < 8; ++i) {
            float xi = x2s[ty * 8 + i];
            #pragma unroll
            for (int j = 0; j < 8; ++j) {
                float dist = (xi + y2s[tx * 8 + j]) - 2.0f * acc[i][j];
                int idx = c0 + tx * 8 + j;
                if (dist < best[i]) { best[i] = dist; bidx[i] = idx; }
            }
        }
    }
    __syncthreads();   // done reading Bs; safe to alias as reduction buffer

    #pragma unroll
    for (int i = 0; i < 8; ++i) {
        redv[(ty * 8 + i) * 16 + tx] = best[i];
        redi[(ty * 8 + i) * 16 + tx] = bidx[i];
    }
    __syncthreads();

    if (tid < 128) {
        float v = redv[tid * 16];
        int  id = redi[tid * 16];
        #pragma unroll
        for (int x = 1; x < 16; ++x) {
            float v2 = redv[tid * 16 + x];
            int   i2 = redi[tid * 16 + x];
            if (v2 < v || (v2 == v && i2 < id)) { v = v2; id = i2; }
        }
        g_dmin[row0 + tid] = v;
        out_ind[row0 + tid] = (float)id;
    }
}

// ---------------------------------------------------------------------------
// Kernel 4: z_q = zf + noise/max(||noise||,1e-9) * sqrt(max(dist_min,0)),
// write z_q in (B, D, H, W) layout, and compute s[b,d] chunk sums for loss.
// One CTA = (b, p) covering 32 rows (two 16-row s-chunks) x 64 dims.
// grid 1024, block 256 (thread = 8 elems: row = t/8, seg = t%8).
// ---------------------------------------------------------------------------
__global__ void zq_kernel(const float* __restrict__ noise, float* __restrict__ out) {
    __shared__ float zq[32 * 65];    // padded rows to dodge bank conflicts
    __shared__ float sred[256];
    int t = threadIdx.x;
    int c = blockIdx.x;
    int b = c >> 5;
    int p = c & 31;
    int r0 = b * 1024 + p * 32;      // first global row of this CTA
    int row = t >> 3;                // 0..31
    int seg = t & 7;                 // 0..7 (8 floats each)
    int n = r0 + row;

    float4 n0 = *(const float4*)&noise[n * 64 + seg * 8];
    float4 n1 = *(const float4*)&noise[n * 64 + seg * 8 + 4];
    float s = n0.x * n0.x + n0.y * n0.y + n0.z * n0.z + n0.w * n0.w
            + n1.x * n1.x + n1.y * n1.y + n1.z * n1.z + n1.w * n1.w;
    // reduce within each 8-lane row group
    s += __shfl_down_sync(0xffffffffu, s, 4, 8);
    s += __shfl_down_sync(0xffffffffu, s, 2, 8);
    s += __shfl_down_sync(0xffffffffu, s, 1, 8);
    float norm2 = __shfl_sync(0xffffffffu, s, 0, 8);

    float dmin = g_dmin[n];
    float scale = sqrtf(fmaxf(dmin, 0.f)) / fmaxf(sqrtf(norm2), 1e-9f);

    float4 z0 = *(const float4*)&g_zf[n * 64 + seg * 8];
    float4 z1 = *(const float4*)&g_zf[n * 64 + seg * 8 + 4];
    float q[8];
    q[0] = z0.x + n0.x * scale;  q[1] = z0.y + n0.y * scale;
    q[2] = z0.z + n0.z * scale;  q[3] = z0.w + n0.w * scale;
    q[4] = z1.x + n1.x * scale;  q[5] = z1.y + n1.y * scale;
    q[6] = z1.z + n1.z * scale;  q[7] = z1.w + n1.w * scale;

    float part = 0.f;
    #pragma unroll
    for (int i = 0; i < 8; ++i) {
        part += q[i];
        zq[row * 65 + seg * 8 + i] = q[i];
    }
    sred[t] = part;
    __syncthreads();

    // two independent 128-thread tree reductions (rows 0-15 | rows 16-31)
    for (int off = 64; off > 0; off >>= 1) {
        if ((t & 127) < off) sred[t] += sred[t + off];
        __syncthreads();
    }
    if (t == 0)   g_s[b * 64 + p * 2 + 0] = sred[0];
    if (t == 128) g_s[b * 64 + p * 2 + 1] = sred[128];

    // write out transposed: out[b*65536 + dd*1024 + p*32 + r]
    int dd = t >> 2;
    int rg = t & 3;
    float4 o0, o1;
    o0.x = zq[(rg * 8 + 0) * 65 + dd];
    o0.y = zq[(rg * 8 + 1) * 65 + dd];
    o0.z = zq[(rg * 8 + 2) * 65 + dd];
    o0.w = zq[(rg * 8 + 3) * 65 + dd];
    o1.x = zq[(rg * 8 + 4) * 65 + dd];
    o1.y = zq[(rg * 8 + 5) * 65 + dd];
    o1.z = zq[(rg * 8 + 6) * 65 + dd];
    o1.w = zq[(rg * 8 + 7) * 65 + dd];
    float* op = out + (size_t)b * 65536 + dd * 1024 + p * 32 + rg * 8;
    *(float4*)op = o0;
    *(float4*)(op + 4) = o1;
}

// ---------------------------------------------------------------------------
// Kernel 5: loss = sum(s^2) / (B * HW^2)
// ---------------------------------------------------------------------------
__global__ void loss_kernel(float* __restrict__ out_loss) {
    __shared__ float sred[256];
    int t = threadIdx.x;
    float a = 0.f;
    #pragma unroll
    for (int i = 0; i < 8; ++i) { float v = g_s[t + i * 256]; a += v * v; }
    sred[t] = a;
    __syncthreads();
    for (int off = 128; off > 0; off >>= 1) {
        if (t < off) sred[t] += sred[t + off];
        __syncthreads();
    }
    if (t == 0) *out_loss = sred[0] * (1.0f / 33554432.0f);  // 1 / (32*1024*1024)
}

// ---------------------------------------------------------------------------
extern "C" void kernel_launch(void* const* d_in, const int* in_sizes, int n_in,
                              void* d_out, int out_size) {
    const float* z     = (const float*)d_in[0];
    const float* cb    = (const float*)d_in[1];
    const float* noise = (const float*)d_in[2];
    float* out      = (float*)d_out;
    float* out_loss = out + ZQ_ELEMS;
    float* out_ind  = out + ZQ_ELEMS + 1;

    cudaFuncSetAttribute(gemm_argmin_kernel,
                         cudaFuncAttributeMaxDynamicSharedMemorySize, GEMM_SMEM);

    transpose_kernel<<<dim3(32, 2, 32), dim3(32, 8)>>>(z);
    y2_kernel<<<4, 256>>>(cb);
    gemm_argmin_kernel<<<256, 256, GEMM_SMEM>>>(cb, out_ind);
    zq_kernel<<<1024, 256>>>(noise, out);
    loss_kernel<<<1, 256>>>(out_loss);
}

// round 3
// speedup vs baseline: 1.2946x; 1.2946x over previous
#include <cuda_runtime.h>
#include <math.h>
#include <stdint.h>

// Problem constants
#define NROWS 32768   // B*H*W
#define DDIM  64
#define MCODE 1024
#define HWSZ  1024
#define ZQ_ELEMS 2097152

// Static device scratch
__device__ float g_zf[NROWS * DDIM];     // (N, D) row-major, transposed z
__device__ float g_mink[NROWS];          // min over codes of (y2 - 2*dot)
__device__ float g_y2[MCODE];
__device__ float g_s[2048];              // s[b,d]
// Codebook packed in mma-fragment order: [chunk(16)][s(8)][ci(64)][t(4)] uint4
//   uint4 = { tf32hi(k0+t), tf32hi(k0+t+4), tf32lo(k0+t), tf32lo(k0+t+4) }
__device__ uint4 g_bpack[16 * 2048];

// ---------------------------------------------------------------------------
// helpers
// ---------------------------------------------------------------------------
__device__ __forceinline__ uint32_t f2tf32(float a) {
    uint32_t r; asm("cvt.rna.tf32.f32 %0, %1;" : "=r"(r) : "f"(a)); return r;
}
__device__ __forceinline__ uint32_t smem_u32(const void* p) {
    uint32_t a;
    asm("{ .reg .u64 t; cvta.to.shared.u64 t, %1; cvt.u32.u64 %0, t; }"
        : "=r"(a) : "l"(p));
    return a;
}
__device__ __forceinline__ void bulk_g2s(uint32_t dst, const void* src,
                                         uint32_t bytes, uint32_t mbar) {
    asm volatile(
        "cp.async.bulk.shared::cta.global.mbarrier::complete_tx::bytes [%0], [%1], %2, [%3];"
        :: "r"(dst), "l"(src), "r"(bytes), "r"(mbar) : "memory");
}
__device__ __forceinline__ void mbar_init(uint32_t mbar, uint32_t cnt) {
    asm volatile("mbarrier.init.shared.b64 [%0], %1;" :: "r"(mbar), "r"(cnt) : "memory");
}
__device__ __forceinline__ void mbar_expect_tx(uint32_t mbar, uint32_t bytes) {
    asm volatile("mbarrier.arrive.expect_tx.shared.b64 _, [%0], %1;"
                 :: "r"(mbar), "r"(bytes) : "memory");
}
__device__ __forceinline__ void mbar_wait(uint32_t mbar, uint32_t parity) {
    uint32_t done;
    asm volatile(
        "{\n\t.reg .pred p;\n\t"
        "mbarrier.try_wait.parity.acquire.cta.shared::cta.b64 p, [%1], %2;\n\t"
        "selp.b32 %0, 1, 0, p;\n\t}"
        : "=r"(done) : "r"(mbar), "r"(parity) : "memory");
    while (!done) {
        asm volatile(
            "{\n\t.reg .pred p;\n\t"
            "mbarrier.try_wait.parity.acquire.cta.shared::cta.b64 p, [%1], %2, 0x989680;\n\t"
            "selp.b32 %0, 1, 0, p;\n\t}"
            : "=r"(done) : "r"(mbar), "r"(parity) : "memory");
    }
}
// D = A(16x8) * B(8x8) + C, tf32, fp32 accum
__device__ __forceinline__ void mma16n8k8(float* c, uint32_t a0, uint32_t a1,
                                          uint32_t a2, uint32_t a3,
                                          uint32_t b0, uint32_t b1) {
    asm volatile(
        "mma.sync.aligned.m16n8k8.row.col.f32.tf32.tf32.f32 "
        "{%0,%1,%2,%3}, {%4,%5,%6,%7}, {%8,%9}, {%0,%1,%2,%3};"
        : "+f"(c[0]), "+f"(c[1]), "+f"(c[2]), "+f"(c[3])
        : "r"(a0), "r"(a1), "r"(a2), "r"(a3), "r"(b0), "r"(b1));
}

// ---------------------------------------------------------------------------
// Kernel 1: transpose z (B,D,H,W) -> zf (N,D)
// ---------------------------------------------------------------------------
__global__ void transpose_kernel(const float* __restrict__ z) {
    __shared__ float tile[32][33];
    int b = blockIdx.z, hw0 = blockIdx.x * 32, d0 = blockIdx.y * 32;
    const float* zb = z + (size_t)b * (DDIM * HWSZ);
    float* ob = g_zf + (size_t)b * (HWSZ * DDIM);
    #pragma unroll
    for (int i = threadIdx.y; i < 32; i += 8)
        tile[i][threadIdx.x] = zb[(d0 + i) * HWSZ + hw0 + threadIdx.x];
    __syncthreads();
    #pragma unroll
    for (int i = threadIdx.y; i < 32; i += 8)
        ob[(hw0 + i) * DDIM + d0 + threadIdx.x] = tile[threadIdx.x][i];
}

// ---------------------------------------------------------------------------
// Kernel 2: per-code squared norms
// ---------------------------------------------------------------------------
__global__ void y2_kernel(const float* __restrict__ cb) {
    int c = blockIdx.x * blockDim.x + threadIdx.x;
    if (c < MCODE) {
        const float4* p = (const float4*)(cb + c * DDIM);
        float s = 0.f;
        #pragma unroll
        for (int q = 0; q < DDIM / 4; ++q) {
            float4 v = p[q];
            s += v.x * v.x + v.y * v.y + v.z * v.z + v.w * v.w;
        }
        g_y2[c] = s;
    }
}

// ---------------------------------------------------------------------------
// Kernel 2b: pack codebook into tf32 hi/lo fragment order.
// One thread per (code c, kstep s, t): 1024*8*4 = 32768 threads.
// ---------------------------------------------------------------------------
__global__ void bprep_kernel(const float* __restrict__ cb) {
    int g = blockIdx.x * 256 + threadIdx.x;
    int c = g >> 5, s = (g >> 2) & 7, t = g & 3;
    float v0 = cb[c * DDIM + s * 8 + t];
    float v1 = cb[c * DDIM + s * 8 + t + 4];
    uint32_t h0 = f2tf32(v0), h1 = f2tf32(v1);
    uint32_t l0 = f2tf32(v0 - __uint_as_float(h0));
    uint32_t l1 = f2tf32(v1 - __uint_as_float(h1));
    int chunk = c >> 6, ci = c & 63;
    g_bpack[chunk * 2048 + s * 256 + ci * 4 + t] = make_uint4(h0, h1, l0, l1);
}

// ---------------------------------------------------------------------------
// Kernel 3: 3xTF32 mma.sync distance GEMM + fused argmin.
// 128 CTAs x 256 rows, 256 threads (8 warps x 32 rows).
// Codes in 16 chunks of 64, B double-buffered via cp.async.bulk.
// smem: mbar(2) | y2[1024] | A4 [8][256][4] uint4 (128KB) | B 2x32KB.
// ---------------------------------------------------------------------------
#define SM_MB   0
#define SM_Y2   128
#define SM_A    4224
#define SM_B    135296
#define GEMM_SMEM 200832

__global__ __launch_bounds__(256, 1)
void gemm_argmin_kernel(float* __restrict__ out_ind) {
    extern __shared__ char sm[];
    uint32_t sb = smem_u32(sm);
    uint4* A4 = (uint4*)(sm + SM_A);
    const float* y2s = (const float*)(sm + SM_Y2);
    int tid = threadIdx.x;
    int wid = tid >> 5, lane = tid & 31;
    int g = lane >> 2, tt = lane & 3;
    int r0 = blockIdx.x * 256;
    int w32 = wid * 32;

    if (tid == 0) {
        mbar_init(sb + SM_MB + 0, 1);
        mbar_init(sb + SM_MB + 8, 1);
    }
    __syncthreads();  // make mbar init visible before bulk ops

    // kick off B chunks 0 and 1
    if (tid == 0) {
        mbar_expect_tx(sb + SM_MB + 0, 32768);
        bulk_g2s(sb + SM_B, g_bpack, 32768, sb + SM_MB + 0);
        mbar_expect_tx(sb + SM_MB + 8, 32768);
        bulk_g2s(sb + SM_B + 32768, g_bpack + 2048, 32768, sb + SM_MB + 8);
    }

    // A prep: pack 256 rows x 64 k into hi/lo tf32 fragment order.
    // q -> (s = q>>10, r = (q>>2)&255, t = q&3)
    #pragma unroll
    for (int it = 0; it < 32; ++it) {
        int q = it * 256 + tid;
        int s = q >> 10, r = (q >> 2) & 255, t = q & 3;
        float v0 = g_zf[(r0 + r) * DDIM + s * 8 + t];
        float v1 = g_zf[(r0 + r) * DDIM + s * 8 + t + 4];
        uint32_t h0 = f2tf32(v0), h1 = f2tf32(v1);
        uint32_t l0 = f2tf32(v0 - __uint_as_float(h0));
        uint32_t l1 = f2tf32(v1 - __uint_as_float(h1));
        A4[s * 1024 + r * 4 + t] = make_uint4(h0, h1, l0, l1);
    }
    for (int i = tid; i < MCODE; i += 256)
        ((float*)(sm + SM_Y2))[i] = g_y2[i];
    __syncthreads();

    float best[4];
    int   bidx[4];
    #pragma unroll
    for (int i = 0; i < 4; ++i) { best[i] = 3.4028235e38f; bidx[i] = 0; }

    for (int t = 0; t < 16; ++t) {
        int buf = t & 1;
        mbar_wait(sb + SM_MB + buf * 8, (t >> 1) & 1);
        const uint4* Bb = (const uint4*)(sm + SM_B + buf * 32768);
        int cbase = t * 64;

        float acc[2][8][4];
        #pragma unroll
        for (int m = 0; m < 2; ++m)
            #pragma unroll
            for (int j = 0; j < 8; ++j)
                #pragma unroll
                for (int e = 0; e < 4; ++e) acc[m][j][e] = 0.f;

        #pragma unroll
        for (int s = 0; s < 8; ++s) {
            // A fragments for this kstep (rows w32.., hi+lo packed)
            uint4 pa0 = A4[s * 1024 + (w32 + g) * 4 + tt];        // m0, rows g
            uint4 pa1 = A4[s * 1024 + (w32 + 8 + g) * 4 + tt];    // m0, rows g+8
            uint4 pa2 = A4[s * 1024 + (w32 + 16 + g) * 4 + tt];   // m1
            uint4 pa3 = A4[s * 1024 + (w32 + 24 + g) * 4 + tt];
            #pragma unroll
            for (int j = 0; j < 8; ++j) {
                uint4 bq = Bb[s * 256 + (j * 8 + g) * 4 + tt];    // {bH0,bH1,bL0,bL1}
                // mtile 0: aH = {pa0.x, pa1.x, pa0.y, pa1.y}, aL = {pa0.z, pa1.z, pa0.w, pa1.w}
                mma16n8k8(acc[0][j], pa0.x, pa1.x, pa0.y, pa1.y, bq.x, bq.y);   // hi*hi
                mma16n8k8(acc[0][j], pa0.x, pa1.x, pa0.y, pa1.y, bq.z, bq.w);   // hi*lo
                mma16n8k8(acc[0][j], pa0.z, pa1.z, pa0.w, pa1.w, bq.x, bq.y);   // lo*hi
                // mtile 1
                mma16n8k8(acc[1][j], pa2.x, pa3.x, pa2.y, pa3.y, bq.x, bq.y);
                mma16n8k8(acc[1][j], pa2.x, pa3.x, pa2.y, pa3.y, bq.z, bq.w);
                mma16n8k8(acc[1][j], pa2.z, pa3.z, pa2.w, pa3.w, bq.x, bq.y);
            }
        }

        // epilogue: key = y2 - 2*dot, running argmin
        #pragma unroll
        for (int j = 0; j < 8; ++j) {
            int c = cbase + j * 8 + 2 * tt;
            float2 y = ((const float2*)y2s)[c >> 1];
            #pragma unroll
            for (int m = 0; m < 2; ++m) {
                float k0 = fmaf(acc[m][j][0], -2.0f, y.x);
                float k1 = fmaf(acc[m][j][1], -2.0f, y.y);
                float k2 = fmaf(acc[m][j][2], -2.0f, y.x);
                float k3 = fmaf(acc[m][j][3], -2.0f, y.y);
                if (k0 < best[m * 2 + 0]) { best[m * 2 + 0] = k0; bidx[m * 2 + 0] = c; }
                if (k1 < best[m * 2 + 0]) { best[m * 2 + 0] = k1; bidx[m * 2 + 0] = c + 1; }
                if (k2 < best[m * 2 + 1]) { best[m * 2 + 1] = k2; bidx[m * 2 + 1] = c; }
                if (k3 < best[m * 2 + 1]) { best[m * 2 + 1] = k3; bidx[m * 2 + 1] = c + 1; }
            }
        }

        __syncthreads();  // everyone done with buf before refill
        if (t + 2 < 16 && tid == 0) {
            mbar_expect_tx(sb + SM_MB + buf * 8, 32768);
            bulk_g2s(sb + SM_B + buf * 32768, g_bpack + (t + 2) * 2048, 32768,
                     sb + SM_MB + buf * 8);
        }
    }

    // cross-lane (t-group) argmin reduce; lane with tt==0 owns the row
    #pragma unroll
    for (int m = 0; m < 4; ++m) {
        float v = best[m];
        int id = bidx[m];
        #pragma unroll
        for (int d = 1; d < 4; d <<= 1) {
            float v2 = __shfl_xor_sync(0xffffffffu, v, d);
            int   i2 = __shfl_xor_sync(0xffffffffu, id, d);
            if (v2 < v || (v2 == v && i2 < id)) { v = v2; id = i2; }
        }
        if (tt == 0) {
            int row = r0 + w32 + (m >> 1) * 16 + (m & 1) * 8 + g;
            g_mink[row] = v;
            out_ind[row] = (float)id;
        }
    }
}

// ---------------------------------------------------------------------------
// Kernel 4: z_q, output transpose, chunk sums; dist_min = x2 + minkey
// ---------------------------------------------------------------------------
__global__ void zq_kernel(const float* __restrict__ noise, float* __restrict__ out) {
    __shared__ float zq[32 * 65];
    __shared__ float sred[256];
    int t = threadIdx.x;
    int c = blockIdx.x;
    int b = c >> 5;
    int p = c & 31;
    int r0 = b * 1024 + p * 32;
    int row = t >> 3;
    int seg = t & 7;
    int n = r0 + row;

    float4 n0 = *(const float4*)&noise[n * 64 + seg * 8];
    float4 n1 = *(const float4*)&noise[n * 64 + seg * 8 + 4];
    float4 z0 = *(const float4*)&g_zf[n * 64 + seg * 8];
    float4 z1 = *(const float4*)&g_zf[n * 64 + seg * 8 + 4];

    float s = n0.x * n0.x + n0.y * n0.y + n0.z * n0.z + n0.w * n0.w
            + n1.x * n1.x + n1.y * n1.y + n1.z * n1.z + n1.w * n1.w;
    float xs = z0.x * z0.x + z0.y * z0.y + z0.z * z0.z + z0.w * z0.w
             + z1.x * z1.x + z1.y * z1.y + z1.z * z1.z + z1.w * z1.w;
    s += __shfl_down_sync(0xffffffffu, s, 4, 8);
    xs += __shfl_down_sync(0xffffffffu, xs, 4, 8);
    s += __shfl_down_sync(0xffffffffu, s, 2, 8);
    xs += __shfl_down_sync(0xffffffffu, xs, 2, 8);
    s += __shfl_down_sync(0xffffffffu, s, 1, 8);
    xs += __shfl_down_sync(0xffffffffu, xs, 1, 8);
    float norm2 = __shfl_sync(0xffffffffu, s, 0, 8);
    float x2 = __shfl_sync(0xffffffffu, xs, 0, 8);

    float dmin = x2 + g_mink[n];
    float scale = sqrtf(fmaxf(dmin, 0.f)) / fmaxf(sqrtf(norm2), 1e-9f);

    float q[8];
    q[0] = z0.x + n0.x * scale;  q[1] = z0.y + n0.y * scale;
    q[2] = z0.z + n0.z * scale;  q[3] = z0.w + n0.w * scale;
    q[4] = z1.x + n1.x * scale;  q[5] = z1.y + n1.y * scale;
    q[6] = z1.z + n1.z * scale;  q[7] = z1.w + n1.w * scale;

    float part = 0.f;
    #pragma unroll
    for (int i = 0; i < 8; ++i) {
        part += q[i];
        zq[row * 65 + seg * 8 + i] = q[i];
    }
    sred[t] = part;
    __syncthreads();

    for (int off = 64; off > 0; off >>= 1) {
        if ((t & 127) < off) sred[t] += sred[t + off];
        __syncthreads();
    }
    if (t == 0)   g_s[b * 64 + p * 2 + 0] = sred[0];
    if (t == 128) g_s[b * 64 + p * 2 + 1] = sred[128];

    int dd = t >> 2;
    int rg = t & 3;
    float4 o0, o1;
    o0.x = zq[(rg * 8 + 0) * 65 + dd];
    o0.y = zq[(rg * 8 + 1) * 65 + dd];
    o0.z = zq[(rg * 8 + 2) * 65 + dd];
    o0.w = zq[(rg * 8 + 3) * 65 + dd];
    o1.x = zq[(rg * 8 + 4) * 65 + dd];
    o1.y = zq[(rg * 8 + 5) * 65 + dd];
    o1.z = zq[(rg * 8 + 6) * 65 + dd];
    o1.w = zq[(rg * 8 + 7) * 65 + dd];
    float* op = out + (size_t)b * 65536 + dd * 1024 + p * 32 + rg * 8;
    *(float4*)op = o0;
    *(float4*)(op + 4) = o1;
}

// ---------------------------------------------------------------------------
// Kernel 5: loss
// ---------------------------------------------------------------------------
__global__ void loss_kernel(float* __restrict__ out_loss) {
    __shared__ float sred[256];
    int t = threadIdx.x;
    float a = 0.f;
    #pragma unroll
    for (int i = 0; i < 8; ++i) { float v = g_s[t + i * 256]; a += v * v; }
    sred[t] = a;
    __syncthreads();
    for (int off = 128; off > 0; off >>= 1) {
        if (t < off) sred[t] += sred[t + off];
        __syncthreads();
    }
    if (t == 0) *out_loss = sred[0] * (1.0f / 33554432.0f);
}

// ---------------------------------------------------------------------------
extern "C" void kernel_launch(void* const* d_in, const int* in_sizes, int n_in,
                              void* d_out, int out_size) {
    const float* z     = (const float*)d_in[0];
    const float* cb    = (const float*)d_in[1];
    const float* noise = (const float*)d_in[2];
    float* out      = (float*)d_out;
    float* out_loss = out + ZQ_ELEMS;
    float* out_ind  = out + ZQ_ELEMS + 1;

    cudaFuncSetAttribute(gemm_argmin_kernel,
                         cudaFuncAttributeMaxDynamicSharedMemorySize, GEMM_SMEM);

    transpose_kernel<<<dim3(32, 2, 32), dim3(32, 8)>>>(z);
    y2_kernel<<<4, 256>>>(cb);
    bprep_kernel<<<128, 256>>>(cb);
    gemm_argmin_kernel<<<128, 256, GEMM_SMEM>>>(out_ind);
    zq_kernel<<<1024, 256>>>(noise, out);
    loss_kernel<<<1, 256>>>(out_loss);
}

// round 4
// speedup vs baseline: 1.4027x; 1.0835x over previous
#include <cuda_runtime.h>
#include <math.h>
#include <stdint.h>

// Problem constants
#define NROWS 32768   // B*H*W
#define DDIM  64
#define MCODE 1024
#define HWSZ  1024
#define ZQ_ELEMS 2097152

// Static device scratch
__device__ float g_mink[NROWS];          // min over codes of (y2 - 2*dot)
__device__ float g_y2[MCODE];
__device__ float g_s[2048];              // s[b,d]
// Codebook packed in mma-fragment order: [chunk(16)][s(8)][ci(64)][t(4)] uint4
//   uint4 = { tf32hi(k0+t), tf32hi(k0+t+4), tf32lo(k0+t), tf32lo(k0+t+4) }
__device__ uint4 g_bpack[16 * 2048];

// ---------------------------------------------------------------------------
// helpers
// ---------------------------------------------------------------------------
__device__ __forceinline__ uint32_t f2tf32(float a) {
    uint32_t r; asm("cvt.rna.tf32.f32 %0, %1;" : "=r"(r) : "f"(a)); return r;
}
__device__ __forceinline__ uint32_t smem_u32(const void* p) {
    uint32_t a;
    asm("{ .reg .u64 t; cvta.to.shared.u64 t, %1; cvt.u32.u64 %0, t; }"
        : "=r"(a) : "l"(p));
    return a;
}
__device__ __forceinline__ void bulk_g2s(uint32_t dst, const void* src,
                                         uint32_t bytes, uint32_t mbar) {
    asm volatile(
        "cp.async.bulk.shared::cta.global.mbarrier::complete_tx::bytes [%0], [%1], %2, [%3];"
        :: "r"(dst), "l"(src), "r"(bytes), "r"(mbar) : "memory");
}
__device__ __forceinline__ void mbar_init(uint32_t mbar, uint32_t cnt) {
    asm volatile("mbarrier.init.shared.b64 [%0], %1;" :: "r"(mbar), "r"(cnt) : "memory");
}
__device__ __forceinline__ void mbar_expect_tx(uint32_t mbar, uint32_t bytes) {
    asm volatile("mbarrier.arrive.expect_tx.shared.b64 _, [%0], %1;"
                 :: "r"(mbar), "r"(bytes) : "memory");
}
__device__ __forceinline__ void mbar_wait(uint32_t mbar, uint32_t parity) {
    uint32_t done;
    asm volatile(
        "{\n\t.reg .pred p;\n\t"
        "mbarrier.try_wait.parity.acquire.cta.shared::cta.b64 p, [%1], %2;\n\t"
        "selp.b32 %0, 1, 0, p;\n\t}"
        : "=r"(done) : "r"(mbar), "r"(parity) : "memory");
    while (!done) {
        asm volatile(
            "{\n\t.reg .pred p;\n\t"
            "mbarrier.try_wait.parity.acquire.cta.shared::cta.b64 p, [%1], %2, 0x989680;\n\t"
            "selp.b32 %0, 1, 0, p;\n\t}"
            : "=r"(done) : "r"(mbar), "r"(parity) : "memory");
    }
}
// D = A(16x8) * B(8x8) + C, tf32, fp32 accum
__device__ __forceinline__ void mma16n8k8(float* c, uint32_t a0, uint32_t a1,
                                          uint32_t a2, uint32_t a3,
                                          uint32_t b0, uint32_t b1) {
    asm volatile(
        "mma.sync.aligned.m16n8k8.row.col.f32.tf32.tf32.f32 "
        "{%0,%1,%2,%3}, {%4,%5,%6,%7}, {%8,%9}, {%0,%1,%2,%3};"
        : "+f"(c[0]), "+f"(c[1]), "+f"(c[2]), "+f"(c[3])
        : "r"(a0), "r"(a1), "r"(a2), "r"(a3), "r"(b0), "r"(b1));
}

// ---------------------------------------------------------------------------
// Kernel 2: per-code squared norms
// ---------------------------------------------------------------------------
__global__ void y2_kernel(const float* __restrict__ cb) {
    int c = blockIdx.x * blockDim.x + threadIdx.x;
    if (c < MCODE) {
        const float4* p = (const float4*)(cb + c * DDIM);
        float s = 0.f;
        #pragma unroll
        for (int q = 0; q < DDIM / 4; ++q) {
            float4 v = p[q];
            s += v.x * v.x + v.y * v.y + v.z * v.z + v.w * v.w;
        }
        g_y2[c] = s;
    }
}

// ---------------------------------------------------------------------------
// Kernel 2b: pack codebook into tf32 hi/lo fragment order.
// ---------------------------------------------------------------------------
__global__ void bprep_kernel(const float* __restrict__ cb) {
    int g = blockIdx.x * 256 + threadIdx.x;
    int c = g >> 5, s = (g >> 2) & 7, t = g & 3;
    float v0 = cb[c * DDIM + s * 8 + t];
    float v1 = cb[c * DDIM + s * 8 + t + 4];
    uint32_t h0 = f2tf32(v0), h1 = f2tf32(v1);
    uint32_t l0 = f2tf32(v0 - __uint_as_float(h0));
    uint32_t l1 = f2tf32(v1 - __uint_as_float(h1));
    int chunk = c >> 6, ci = c & 63;
    g_bpack[chunk * 2048 + s * 256 + ci * 4 + t] = make_uint4(h0, h1, l0, l1);
}

// ---------------------------------------------------------------------------
// Kernel 3: 3xTF32 mma.sync distance GEMM + fused argmin.
// 128 CTAs x 256 rows, 512 threads (16 warps x 16 rows).
// A read DIRECTLY from z (coalesced: rows = contiguous hw of one batch).
// Codes in 16 chunks of 64, B double-buffered via cp.async.bulk.
// smem: mbar(2) | y2[1024] | A4 [8][256][4] uint4 (128KB) | B 2x32KB.
// ---------------------------------------------------------------------------
#define SM_MB   0
#define SM_Y2   128
#define SM_A    4224
#define SM_B    135296
#define GEMM_SMEM 200832

__global__ __launch_bounds__(512, 1)
void gemm_argmin_kernel(const float* __restrict__ z, float* __restrict__ out_ind) {
    extern __shared__ char sm[];
    uint32_t sb = smem_u32(sm);
    uint4* A4 = (uint4*)(sm + SM_A);
    const float* y2s = (const float*)(sm + SM_Y2);
    int tid = threadIdx.x;
    int wid = tid >> 5, lane = tid & 31;
    int g = lane >> 2, tt = lane & 3;
    int r0 = blockIdx.x * 256;
    int w16 = wid * 16;

    if (tid == 0) {
        mbar_init(sb + SM_MB + 0, 1);
        mbar_init(sb + SM_MB + 8, 1);
    }
    __syncthreads();  // make mbar init visible before bulk ops

    // kick off B chunks 0 and 1
    if (tid == 0) {
        mbar_expect_tx(sb + SM_MB + 0, 32768);
        bulk_g2s(sb + SM_B, g_bpack, 32768, sb + SM_MB + 0);
        mbar_expect_tx(sb + SM_MB + 8, 32768);
        bulk_g2s(sb + SM_B + 32768, g_bpack + 2048, 32768, sb + SM_MB + 8);
    }

    // A prep: read z[b, d, hw0 + r] directly (coalesced), pack hi/lo tf32
    // fragment order. CTA rows = b = blk>>2, hw = (blk&3)*256 + r.
    {
        const float* zb = z + (size_t)(blockIdx.x >> 2) * (DDIM * HWSZ)
                            + (blockIdx.x & 3) * 256;
        int r = tid & 255, half = tid >> 8;
        #pragma unroll
        for (int it = 0; it < 16; ++it) {
            int dd = it * 2 + half;            // 0..31
            int s = dd >> 2, t = dd & 3;
            float v0 = zb[(s * 8 + t) * HWSZ + r];
            float v1 = zb[(s * 8 + t + 4) * HWSZ + r];
            uint32_t h0 = f2tf32(v0), h1 = f2tf32(v1);
            uint32_t l0 = f2tf32(v0 - __uint_as_float(h0));
            uint32_t l1 = f2tf32(v1 - __uint_as_float(h1));
            A4[s * 1024 + r * 4 + t] = make_uint4(h0, h1, l0, l1);
        }
    }
    for (int i = tid; i < MCODE; i += 512)
        ((float*)(sm + SM_Y2))[i] = g_y2[i];
    __syncthreads();

    float best[2];
    int   bidx[2];
    best[0] = best[1] = 3.4028235e38f;
    bidx[0] = bidx[1] = 0;

    for (int t = 0; t < 16; ++t) {
        int buf = t & 1;
        mbar_wait(sb + SM_MB + buf * 8, (t >> 1) & 1);
        const uint4* Bb = (const uint4*)(sm + SM_B + buf * 32768);
        int cbase = t * 64;

        float acc[8][4];
        #pragma unroll
        for (int j = 0; j < 8; ++j)
            #pragma unroll
            for (int e = 0; e < 4; ++e) acc[j][e] = 0.f;

        #pragma unroll
        for (int s = 0; s < 8; ++s) {
            uint4 pa0 = A4[s * 1024 + (w16 + g) * 4 + tt];      // rows g
            uint4 pa1 = A4[s * 1024 + (w16 + 8 + g) * 4 + tt];  // rows g+8
            #pragma unroll
            for (int j = 0; j < 8; ++j) {
                uint4 bq = Bb[s * 256 + (j * 8 + g) * 4 + tt];  // {bH0,bH1,bL0,bL1}
                mma16n8k8(acc[j], pa0.x, pa1.x, pa0.y, pa1.y, bq.x, bq.y);  // hi*hi
                mma16n8k8(acc[j], pa0.x, pa1.x, pa0.y, pa1.y, bq.z, bq.w);  // hi*lo
                mma16n8k8(acc[j], pa0.z, pa1.z, pa0.w, pa1.w, bq.x, bq.y);  // lo*hi
            }
        }

        // epilogue: key = y2 - 2*dot, running argmin
        #pragma unroll
        for (int j = 0; j < 8; ++j) {
            int c = cbase + j * 8 + 2 * tt;
            float2 y = ((const float2*)y2s)[c >> 1];
            float k0 = fmaf(acc[j][0], -2.0f, y.x);
            float k1 = fmaf(acc[j][1], -2.0f, y.y);
            float k2 = fmaf(acc[j][2], -2.0f, y.x);
            float k3 = fmaf(acc[j][3], -2.0f, y.y);
            if (k0 < best[0]) { best[0] = k0; bidx[0] = c; }
            if (k1 < best[0]) { best[0] = k1; bidx[0] = c + 1; }
            if (k2 < best[1]) { best[1] = k2; bidx[1] = c; }
            if (k3 < best[1]) { best[1] = k3; bidx[1] = c + 1; }
        }

        __syncthreads();  // everyone done with buf before refill
        if (t + 2 < 16 && tid == 0) {
            mbar_expect_tx(sb + SM_MB + buf * 8, 32768);
            bulk_g2s(sb + SM_B + buf * 32768, g_bpack + (t + 2) * 2048, 32768,
                     sb + SM_MB + buf * 8);
        }
    }

    // cross-lane (t-group) argmin reduce; lane with tt==0 owns the row
    #pragma unroll
    for (int m = 0; m < 2; ++m) {
        float v = best[m];
        int id = bidx[m];
        #pragma unroll
        for (int d = 1; d < 4; d <<= 1) {
            float v2 = __shfl_xor_sync(0xffffffffu, v, d);
            int   i2 = __shfl_xor_sync(0xffffffffu, id, d);
            if (v2 < v || (v2 == v && i2 < id)) { v = v2; id = i2; }
        }
        if (tt == 0) {
            int row = r0 + w16 + m * 8 + g;
            g_mink[row] = v;
            out_ind[row] = (float)id;
        }
    }
}

// ---------------------------------------------------------------------------
// Kernel 4: z_q, output transpose, chunk sums; dist_min = x2 + minkey.
// Reads z directly through a smem transpose tile (no g_zf).
// ---------------------------------------------------------------------------
__global__ void zq_kernel(const float* __restrict__ z,
                          const float* __restrict__ noise,
                          float* __restrict__ out) {
    __shared__ float zt[64][33];     // z[b, d, hw0+w] tile
    __shared__ float zq[32 * 65];
    __shared__ float sred[256];
    int t = threadIdx.x;
    int c = blockIdx.x;
    int b = c >> 5;
    int p = c & 31;
    int r0 = b * 1024 + p * 32;

    // load z tile: 64 d x 32 hw, coalesced over hw
    {
        const float* zb = z + (size_t)b * 65536 + p * 32;
        int w = t & 31, db = t >> 5;
        #pragma unroll
        for (int it = 0; it < 8; ++it) {
            int d = it * 8 + db;
            zt[d][w] = zb[d * 1024 + w];
        }
    }
    __syncthreads();

    int row = t >> 3;
    int seg = t & 7;
    int n = r0 + row;

    float4 n0 = *(const float4*)&noise[n * 64 + seg * 8];
    float4 n1 = *(const float4*)&noise[n * 64 + seg * 8 + 4];
    float nv[8] = {n0.x, n0.y, n0.z, n0.w, n1.x, n1.y, n1.z, n1.w};
    float zv[8];
    #pragma unroll
    for (int i = 0; i < 8; ++i) zv[i] = zt[seg * 8 + i][row];

    float s = 0.f, xs = 0.f;
    #pragma unroll
    for (int i = 0; i < 8; ++i) { s += nv[i] * nv[i]; xs += zv[i] * zv[i]; }
    s += __shfl_down_sync(0xffffffffu, s, 4, 8);
    xs += __shfl_down_sync(0xffffffffu, xs, 4, 8);
    s += __shfl_down_sync(0xffffffffu, s, 2, 8);
    xs += __shfl_down_sync(0xffffffffu, xs, 2, 8);
    s += __shfl_down_sync(0xffffffffu, s, 1, 8);
    xs += __shfl_down_sync(0xffffffffu, xs, 1, 8);
    float norm2 = __shfl_sync(0xffffffffu, s, 0, 8);
    float x2 = __shfl_sync(0xffffffffu, xs, 0, 8);

    float dmin = x2 + g_mink[n];
    float scale = sqrtf(fmaxf(dmin, 0.f)) / fmaxf(sqrtf(norm2), 1e-9f);

    float part = 0.f;
    #pragma unroll
    for (int i = 0; i < 8; ++i) {
        float q = zv[i] + nv[i] * scale;
        part += q;
        zq[row * 65 + seg * 8 + i] = q;
    }
    sred[t] = part;
    __syncthreads();

    for (int off = 64; off > 0; off >>= 1) {
        if ((t & 127) < off) sred[t] += sred[t + off];
        __syncthreads();
    }
    if (t == 0)   g_s[b * 64 + p * 2 + 0] = sred[0];
    if (t == 128) g_s[b * 64 + p * 2 + 1] = sred[128];

    int dd = t >> 2;
    int rg = t & 3;
    float4 o0, o1;
    o0.x = zq[(rg * 8 + 0) * 65 + dd];
    o0.y = zq[(rg * 8 + 1) * 65 + dd];
    o0.z = zq[(rg * 8 + 2) * 65 + dd];
    o0.w = zq[(rg * 8 + 3) * 65 + dd];
    o1.x = zq[(rg * 8 + 4) * 65 + dd];
    o1.y = zq[(rg * 8 + 5) * 65 + dd];
    o1.z = zq[(rg * 8 + 6) * 65 + dd];
    o1.w = zq[(rg * 8 + 7) * 65 + dd];
    float* op = out + (size_t)b * 65536 + dd * 1024 + p * 32 + rg * 8;
    *(float4*)op = o0;
    *(float4*)(op + 4) = o1;
}

// ---------------------------------------------------------------------------
// Kernel 5: loss
// ---------------------------------------------------------------------------
__global__ void loss_kernel(float* __restrict__ out_loss) {
    __shared__ float sred[256];
    int t = threadIdx.x;
    float a = 0.f;
    #pragma unroll
    for (int i = 0; i < 8; ++i) { float v = g_s[t + i * 256]; a += v * v; }
    sred[t] = a;
    __syncthreads();
    for (int off = 128; off > 0; off >>= 1) {
        if (t < off) sred[t] += sred[t + off];
        __syncthreads();
    }
    if (t == 0) *out_loss = sred[0] * (1.0f / 33554432.0f);
}

// ---------------------------------------------------------------------------
extern "C" void kernel_launch(void* const* d_in, const int* in_sizes, int n_in,
                              void* d_out, int out_size) {
    const float* z     = (const float*)d_in[0];
    const float* cb    = (const float*)d_in[1];
    const float* noise = (const float*)d_in[2];
    float* out      = (float*)d_out;
    float* out_loss = out + ZQ_ELEMS;
    float* out_ind  = out + ZQ_ELEMS + 1;

    cudaFuncSetAttribute(gemm_argmin_kernel,
                         cudaFuncAttributeMaxDynamicSharedMemorySize, GEMM_SMEM);

    y2_kernel<<<4, 256>>>(cb);
    bprep_kernel<<<128, 256>>>(cb);
    gemm_argmin_kernel<<<128, 512, GEMM_SMEM>>>(z, out_ind);
    zq_kernel<<<1024, 256>>>(z, noise, out);
    loss_kernel<<<1, 256>>>(out_loss);
}

// round 5
// speedup vs baseline: 1.6086x; 1.1468x over previous
#include <cuda_runtime.h>
#include <math.h>
#include <stdint.h>

// Problem constants
#define NROWS 32768   // B*H*W
#define DDIM  64
#define MCODE 1024
#define HWSZ  1024
#define ZQ_ELEMS 2097152

// Static device scratch
__device__ float g_key[2 * NROWS];       // per code-half: min key (y2 - 2*dot)
__device__ float g_kidx[2 * NROWS];      // per code-half: argmin index (as float)
__device__ float g_y2[MCODE];
__device__ float g_s[2048];              // s[b,d]
// Codebook packed in mma-fragment order: [chunk(16)][s(8)][ci(64)][t(4)] uint4
//   uint4 = { tf32hi(k0+t), tf32hi(k0+t+4), tf32lo(k0+t), tf32lo(k0+t+4) }
__device__ uint4 g_bpack[16 * 2048];

// ---------------------------------------------------------------------------
// helpers
// ---------------------------------------------------------------------------
__device__ __forceinline__ uint32_t f2tf32(float a) {
    uint32_t r; asm("cvt.rna.tf32.f32 %0, %1;" : "=r"(r) : "f"(a)); return r;
}
__device__ __forceinline__ uint32_t smem_u32(const void* p) {
    uint32_t a;
    asm("{ .reg .u64 t; cvta.to.shared.u64 t, %1; cvt.u32.u64 %0, t; }"
        : "=r"(a) : "l"(p));
    return a;
}
__device__ __forceinline__ void bulk_g2s(uint32_t dst, const void* src,
                                         uint32_t bytes, uint32_t mbar) {
    asm volatile(
        "cp.async.bulk.shared::cta.global.mbarrier::complete_tx::bytes [%0], [%1], %2, [%3];"
        :: "r"(dst), "l"(src), "r"(bytes), "r"(mbar) : "memory");
}
__device__ __forceinline__ void mbar_init(uint32_t mbar, uint32_t cnt) {
    asm volatile("mbarrier.init.shared.b64 [%0], %1;" :: "r"(mbar), "r"(cnt) : "memory");
}
__device__ __forceinline__ void mbar_expect_tx(uint32_t mbar, uint32_t bytes) {
    asm volatile("mbarrier.arrive.expect_tx.shared.b64 _, [%0], %1;"
                 :: "r"(mbar), "r"(bytes) : "memory");
}
__device__ __forceinline__ void mbar_wait(uint32_t mbar, uint32_t parity) {
    uint32_t done;
    asm volatile(
        "{\n\t.reg .pred p;\n\t"
        "mbarrier.try_wait.parity.acquire.cta.shared::cta.b64 p, [%1], %2;\n\t"
        "selp.b32 %0, 1, 0, p;\n\t}"
        : "=r"(done) : "r"(mbar), "r"(parity) : "memory");
    while (!done) {
        asm volatile(
            "{\n\t.reg .pred p;\n\t"
            "mbarrier.try_wait.parity.acquire.cta.shared::cta.b64 p, [%1], %2, 0x989680;\n\t"
            "selp.b32 %0, 1, 0, p;\n\t}"
            : "=r"(done) : "r"(mbar), "r"(parity) : "memory");
    }
}
// D = A(16x8) * B(8x8) + C, tf32, fp32 accum
__device__ __forceinline__ void mma16n8k8(float* c, uint32_t a0, uint32_t a1,
                                          uint32_t a2, uint32_t a3,
                                          uint32_t b0, uint32_t b1) {
    asm volatile(
        "mma.sync.aligned.m16n8k8.row.col.f32.tf32.tf32.f32 "
        "{%0,%1,%2,%3}, {%4,%5,%6,%7}, {%8,%9}, {%0,%1,%2,%3};"
        : "+f"(c[0]), "+f"(c[1]), "+f"(c[2]), "+f"(c[3])
        : "r"(a0), "r"(a1), "r"(a2), "r"(a3), "r"(b0), "r"(b1));
}

// ---------------------------------------------------------------------------
// Kernel 1: pack codebook into tf32 hi/lo fragment order + per-code y2.
// One warp per code: lane = (s,t) covers k = s*8+t and s*8+t+4.
// ---------------------------------------------------------------------------
__global__ void bprep_kernel(const float* __restrict__ cb) {
    int g = blockIdx.x * 256 + threadIdx.x;
    int c = g >> 5, s = (g >> 2) & 7, t = g & 3;
    float v0 = cb[c * DDIM + s * 8 + t];
    float v1 = cb[c * DDIM + s * 8 + t + 4];
    uint32_t h0 = f2tf32(v0), h1 = f2tf32(v1);
    uint32_t l0 = f2tf32(v0 - __uint_as_float(h0));
    uint32_t l1 = f2tf32(v1 - __uint_as_float(h1));
    int chunk = c >> 6, ci = c & 63;
    g_bpack[chunk * 2048 + ci * 4 + s * 256 + t] = make_uint4(h0, h1, l0, l1);
    // y2: warp-reduce v0^2 + v1^2 across the 32 lanes of this code
    float y = v0 * v0 + v1 * v1;
    #pragma unroll
    for (int d = 16; d > 0; d >>= 1)
        y += __shfl_xor_sync(0xffffffffu, y, d);
    if ((threadIdx.x & 31) == 0) g_y2[c] = y;
}

// ---------------------------------------------------------------------------
// Kernel 2: 3xTF32 mma.sync distance GEMM + fused argmin.
// Grid 128: bit0 = code half (512 codes), bits1+ = row block (512 rows).
// 512 threads = 16 warps x 32 rows. 8 chunks of 64 codes, B double-buffered.
// A kept in smem as raw fp32 pairs (128 KB), split to tf32 hi/lo in regs.
// smem: mbar(16) | y2[512] | A2 float2[8][512][4] (128KB) | B 2x32KB.
// ---------------------------------------------------------------------------
#define SM_MB   0
#define SM_Y2   128
#define SM_A    2176
#define SM_B    133248
#define GEMM_SMEM 198784

__global__ __launch_bounds__(512, 1)
void gemm_argmin_kernel(const float* __restrict__ z) {
    extern __shared__ char sm[];
    uint32_t sb = smem_u32(sm);
    float2* A2 = (float2*)(sm + SM_A);
    const float* y2s = (const float*)(sm + SM_Y2);
    int tid = threadIdx.x;
    int wid = tid >> 5, lane = tid & 31;
    int g = lane >> 2, tt = lane & 3;
    int half = blockIdx.x & 1;
    int rb = blockIdx.x >> 1;            // 0..63
    int r0 = rb * 512;
    int w32 = wid * 32;
    const uint4* bsrc = g_bpack + half * 8 * 2048;

    if (tid == 0) {
        mbar_init(sb + SM_MB + 0, 1);
        mbar_init(sb + SM_MB + 8, 1);
    }
    __syncthreads();  // make mbar init visible before bulk ops

    // kick off B chunks 0 and 1
    if (tid == 0) {
        mbar_expect_tx(sb + SM_MB + 0, 32768);
        bulk_g2s(sb + SM_B, bsrc, 32768, sb + SM_MB + 0);
        mbar_expect_tx(sb + SM_MB + 8, 32768);
        bulk_g2s(sb + SM_B + 32768, bsrc + 2048, 32768, sb + SM_MB + 8);
    }

    // A prep: z[b, d, hw0 + r] -> A2[(s*512 + r)*4 + t] = {f(k=8s+t), f(k=8s+t+4)}
    // Warp covers 8 rows x 4 t; 4 passes of 128 rows. STS float2 contiguous.
    {
        const float* zb = z + (size_t)(rb >> 1) * (DDIM * HWSZ) + (rb & 1) * 512;
        int roff = lane >> 2, tp = lane & 3;
        #pragma unroll
        for (int p = 0; p < 4; ++p) {
            int r = p * 128 + wid * 8 + roff;
            #pragma unroll
            for (int s = 0; s < 8; ++s) {
                float v0 = zb[(s * 8 + tp) * HWSZ + r];
                float v1 = zb[(s * 8 + tp + 4) * HWSZ + r];
                A2[(s * 512 + r) * 4 + tp] = make_float2(v0, v1);
            }
        }
    }
    for (int i = tid; i < 512; i += 512)
        ((float*)(sm + SM_Y2))[i] = g_y2[half * 512 + i];
    __syncthreads();

    float best[4];
    int   bidx[4];
    #pragma unroll
    for (int i = 0; i < 4; ++i) { best[i] = 3.4028235e38f; bidx[i] = 0; }

    for (int ch = 0; ch < 8; ++ch) {
        int buf = ch & 1;
        mbar_wait(sb + SM_MB + buf * 8, (ch >> 1) & 1);
        const uint4* Bb = (const uint4*)(sm + SM_B + buf * 32768);

        float acc[2][8][4];
        #pragma unroll
        for (int m = 0; m < 2; ++m)
            #pragma unroll
            for (int j = 0; j < 8; ++j)
                #pragma unroll
                for (int e = 0; e < 4; ++e) acc[m][j][e] = 0.f;

        #pragma unroll
        for (int s = 0; s < 8; ++s) {
            float2 f0 = A2[(s * 512 + w32 + g) * 4 + tt];        // rows g
            float2 f1 = A2[(s * 512 + w32 + 8 + g) * 4 + tt];    // rows g+8
            float2 f2 = A2[(s * 512 + w32 + 16 + g) * 4 + tt];   // rows g+16
            float2 f3 = A2[(s * 512 + w32 + 24 + g) * 4 + tt];   // rows g+24
            // split to tf32 hi/lo
            uint32_t h0x = f2tf32(f0.x), h0y = f2tf32(f0.y);
            uint32_t h1x = f2tf32(f1.x), h1y = f2tf32(f1.y);
            uint32_t h2x = f2tf32(f2.x), h2y = f2tf32(f2.y);
            uint32_t h3x = f2tf32(f3.x), h3y = f2tf32(f3.y);
            uint32_t l0x = f2tf32(f0.x - __uint_as_float(h0x));
            uint32_t l0y = f2tf32(f0.y - __uint_as_float(h0y));
            uint32_t l1x = f2tf32(f1.x - __uint_as_float(h1x));
            uint32_t l1y = f2tf32(f1.y - __uint_as_float(h1y));
            uint32_t l2x = f2tf32(f2.x - __uint_as_float(h2x));
            uint32_t l2y = f2tf32(f2.y - __uint_as_float(h2y));
            uint32_t l3x = f2tf32(f3.x - __uint_as_float(h3x));
            uint32_t l3y = f2tf32(f3.y - __uint_as_float(h3y));
            #pragma unroll
            for (int j = 0; j < 8; ++j) {
                uint4 bq = Bb[s * 256 + (j * 8 + g) * 4 + tt];   // {bH0,bH1,bL0,bL1}
                // m-tile 0 (rows w32 .. w32+15)
                mma16n8k8(acc[0][j], h0x, h1x, h0y, h1y, bq.x, bq.y);  // hi*hi
                mma16n8k8(acc[0][j], h0x, h1x, h0y, h1y, bq.z, bq.w);  // hi*lo
                mma16n8k8(acc[0][j], l0x, l1x, l0y, l1y, bq.x, bq.y);  // lo*hi
                // m-tile 1 (rows w32+16 .. w32+31)
                mma16n8k8(acc[1][j], h2x, h3x, h2y, h3y, bq.x, bq.y);
                mma16n8k8(acc[1][j], h2x, h3x, h2y, h3y, bq.z, bq.w);
                mma16n8k8(acc[1][j], l2x, l3x, l2y, l3y, bq.x, bq.y);
            }
        }

        // epilogue: key = y2 - 2*dot, running argmin (local code index)
        #pragma unroll
        for (int j = 0; j < 8; ++j) {
            int cl = ch * 64 + j * 8 + 2 * tt;
            float2 y = ((const float2*)y2s)[cl >> 1];
            #pragma unroll
            for (int m = 0; m < 2; ++m) {
                float k0 = fmaf(acc[m][j][0], -2.0f, y.x);
                float k1 = fmaf(acc[m][j][1], -2.0f, y.y);
                float k2 = fmaf(acc[m][j][2], -2.0f, y.x);
                float k3 = fmaf(acc[m][j][3], -2.0f, y.y);
                if (k0 < best[m * 2 + 0]) { best[m * 2 + 0] = k0; bidx[m * 2 + 0] = cl; }
                if (k1 < best[m * 2 + 0]) { best[m * 2 + 0] = k1; bidx[m * 2 + 0] = cl + 1; }
                if (k2 < best[m * 2 + 1]) { best[m * 2 + 1] = k2; bidx[m * 2 + 1] = cl; }
                if (k3 < best[m * 2 + 1]) { best[m * 2 + 1] = k3; bidx[m * 2 + 1] = cl + 1; }
            }
        }

        __syncthreads();  // everyone done with buf before refill
        if (ch + 2 < 8 && tid == 0) {
            mbar_expect_tx(sb + SM_MB + buf * 8, 32768);
            bulk_g2s(sb + SM_B + buf * 32768, bsrc + (ch + 2) * 2048, 32768,
                     sb + SM_MB + buf * 8);
        }
    }

    // cross-lane (t-group) argmin reduce; lane with tt==0 owns the row
    #pragma unroll
    for (int m = 0; m < 4; ++m) {
        float v = best[m];
        int id = bidx[m];
        #pragma unroll
        for (int d = 1; d < 4; d <<= 1) {
            float v2 = __shfl_xor_sync(0xffffffffu, v, d);
            int   i2 = __shfl_xor_sync(0xffffffffu, id, d);
            if (v2 < v || (v2 == v && i2 < id)) { v = v2; id = i2; }
        }
        if (tt == 0) {
            int row = r0 + w32 + (m >> 1) * 16 + (m & 1) * 8 + g;
            g_key[half * NROWS + row] = v;
            g_kidx[half * NROWS + row] = (float)(half * 512 + id);
        }
    }
}

// ---------------------------------------------------------------------------
// Kernel 3: z_q, output transpose, chunk sums, ind merge.
// dist_min = x2 + min(key_half0, key_half1); half0 wins ties (lower idx).
// ---------------------------------------------------------------------------
__global__ void zq_kernel(const float* __restrict__ z,
                          const float* __restrict__ noise,
                          float* __restrict__ out,
                          float* __restrict__ out_ind) {
    __shared__ float zt[64][33];     // z[b, d, hw0+w] tile
    __shared__ float zq[32 * 65];
    __shared__ float sred[256];
    int t = threadIdx.x;
    int c = blockIdx.x;
    int b = c >> 5;
    int p = c & 31;
    int r0 = b * 1024 + p * 32;

    // load z tile: 64 d x 32 hw, coalesced over hw
    {
        const float* zb = z + (size_t)b * 65536 + p * 32;
        int w = t & 31, db = t >> 5;
        #pragma unroll
        for (int it = 0; it < 8; ++it) {
            int d = it * 8 + db;
            zt[d][w] = zb[d * 1024 + w];
        }
    }
    __syncthreads();

    int row = t >> 3;
    int seg = t & 7;
    int n = r0 + row;

    float4 n0 = *(const float4*)&noise[n * 64 + seg * 8];
    float4 n1 = *(const float4*)&noise[n * 64 + seg * 8 + 4];
    float nv[8] = {n0.x, n0.y, n0.z, n0.w, n1.x, n1.y, n1.z, n1.w};
    float zv[8];
    #pragma unroll
    for (int i = 0; i < 8; ++i) zv[i] = zt[seg * 8 + i][row];

    float s = 0.f, xs = 0.f;
    #pragma unroll
    for (int i = 0; i < 8; ++i) { s += nv[i] * nv[i]; xs += zv[i] * zv[i]; }
    s += __shfl_down_sync(0xffffffffu, s, 4, 8);
    xs += __shfl_down_sync(0xffffffffu, xs, 4, 8);
    s += __shfl_down_sync(0xffffffffu, s, 2, 8);
    xs += __shfl_down_sync(0xffffffffu, xs, 2, 8);
    s += __shfl_down_sync(0xffffffffu, s, 1, 8);
    xs += __shfl_down_sync(0xffffffffu, xs, 1, 8);
    float norm2 = __shfl_sync(0xffffffffu, s, 0, 8);
    float x2 = __shfl_sync(0xffffffffu, xs, 0, 8);

    // merge the two code-half candidates
    float k0 = g_key[n], k1 = g_key[NROWS + n];
    float mk, mi;
    if (k1 < k0) { mk = k1; mi = g_kidx[NROWS + n]; }
    else         { mk = k0; mi = g_kidx[n]; }
    if (seg == 0) out_ind[n] = mi;

    float dmin = x2 + mk;
    float scale = sqrtf(fmaxf(dmin, 0.f)) / fmaxf(sqrtf(norm2), 1e-9f);

    float part = 0.f;
    #pragma unroll
    for (int i = 0; i < 8; ++i) {
        float q = zv[i] + nv[i] * scale;
        part += q;
        zq[row * 65 + seg * 8 + i] = q;
    }
    sred[t] = part;
    __syncthreads();

    for (int off = 64; off > 0; off >>= 1) {
        if ((t & 127) < off) sred[t] += sred[t + off];
        __syncthreads();
    }
    if (t == 0)   g_s[b * 64 + p * 2 + 0] = sred[0];
    if (t == 128) g_s[b * 64 + p * 2 + 1] = sred[128];

    int dd = t >> 2;
    int rg = t & 3;
    float4 o0, o1;
    o0.x = zq[(rg * 8 + 0) * 65 + dd];
    o0.y = zq[(rg * 8 + 1) * 65 + dd];
    o0.z = zq[(rg * 8 + 2) * 65 + dd];
    o0.w = zq[(rg * 8 + 3) * 65 + dd];
    o1.x = zq[(rg * 8 + 4) * 65 + dd];
    o1.y = zq[(rg * 8 + 5) * 65 + dd];
    o1.z = zq[(rg * 8 + 6) * 65 + dd];
    o1.w = zq[(rg * 8 + 7) * 65 + dd];
    float* op = out + (size_t)b * 65536 + dd * 1024 + p * 32 + rg * 8;
    *(float4*)op = o0;
    *(float4*)(op + 4) = o1;
}

// ---------------------------------------------------------------------------
// Kernel 4: loss
// ---------------------------------------------------------------------------
__global__ void loss_kernel(float* __restrict__ out_loss) {
    __shared__ float sred[256];
    int t = threadIdx.x;
    float a = 0.f;
    #pragma unroll
    for (int i = 0; i < 8; ++i) { float v = g_s[t + i * 256]; a += v * v; }
    sred[t] = a;
    __syncthreads();
    for (int off = 128; off > 0; off >>= 1) {
        if (t < off) sred[t] += sred[t + off];
        __syncthreads();
    }
    if (t == 0) *out_loss = sred[0] * (1.0f / 33554432.0f);
}

// ---------------------------------------------------------------------------
extern "C" void kernel_launch(void* const* d_in, const int* in_sizes, int n_in,
                              void* d_out, int out_size) {
    const float* z     = (const float*)d_in[0];
    const float* cb    = (const float*)d_in[1];
    const float* noise = (const float*)d_in[2];
    float* out      = (float*)d_out;
    float* out_loss = out + ZQ_ELEMS;
    float* out_ind  = out + ZQ_ELEMS + 1;

    cudaFuncSetAttribute(gemm_argmin_kernel,
                         cudaFuncAttributeMaxDynamicSharedMemorySize, GEMM_SMEM);

    bprep_kernel<<<128, 256>>>(cb);
    gemm_argmin_kernel<<<128, 512, GEMM_SMEM>>>(z);
    zq_kernel<<<1024, 256>>>(z, noise, out, out_ind);
    loss_kernel<<<1, 256>>>(out_loss);
}